// round 14
// baseline (speedup 1.0000x reference)
#include <cuda_runtime.h>
#include <cuda_fp16.h>
#include <math.h>

#define NNODE 100000
#define NF 128
#define NCLS 40
#define EMAX 1600000
#define SCB 256   // scan block size

// ---------------------------------------------------------------------------
// Static device scratch
// ---------------------------------------------------------------------------
__device__ __half g_hA[(size_t)NNODE * NF];     // fp16 ping
__device__ __half g_hB[(size_t)NNODE * NF];     // fp16 pong
__device__ __half g_t40h[(size_t)NNODE * NCLS]; // fp16 t = h1 @ W2^T
__device__ __half g_W0h[NF * NF];
__device__ __half g_W1h[NF * NF];
__device__ __half g_W2h[NCLS * NF];
__device__ int    g_rpZ[NNODE + 1];
__device__ int    g_rpA[NNODE + 1];
__device__ int    g_cntZ[NNODE];
__device__ int    g_cntA[NNODE];
__device__ int    g_partZ[(NNODE + SCB - 1) / SCB];
__device__ int    g_partA[(NNODE + SCB - 1) / SCB];
__device__ int    g_slotZ[EMAX];
__device__ int    g_slotA[EMAX];
__device__ int2   g_edgeZ[EMAX];                // {src, val_bits} CSR-ordered
__device__ int2   g_edgeA[EMAX];

__device__ __forceinline__ unsigned f2tf32(float f) {
    unsigned u;
    asm("cvt.rna.tf32.f32 %0, %1;" : "=r"(u) : "f"(f));
    return u;
}

// ---------------------------------------------------------------------------
// Pre-pass: xh = half(M[row] * x)
// ---------------------------------------------------------------------------
__global__ __launch_bounds__(256) void mxhalf_kernel(
    const float* __restrict__ x, const float* __restrict__ M,
    __half* __restrict__ xh, int n)
{
    int i = blockIdx.x * blockDim.x + threadIdx.x;  // one thread per 4 elems
    if (i >= n * (NF / 4)) return;
    int row = i >> 5;
    int col = (i & 31) * 4;
    float m = M[row];
    float4 v = *(const float4*)(x + (size_t)row * NF + col);
    uint2 u;
    *(__half2*)&u.x = __floats2half2_rn(v.x * m, v.y * m);
    *(__half2*)&u.y = __floats2half2_rn(v.z * m, v.w * m);
    *(uint2*)(xh + (size_t)row * NF + col) = u;
}

// ---------------------------------------------------------------------------
// Weight fp32 -> fp16 pre-convert (fp16 mantissa == tf32 mantissa; exact
// fp16->float in the GEMM, so effective rounding unchanged)
// ---------------------------------------------------------------------------
__global__ void w2h_kernel(const float* __restrict__ W, __half* __restrict__ Wh, int sz4) {
    int i = blockIdx.x * blockDim.x + threadIdx.x;
    if (i >= sz4) return;
    float4 v = *(const float4*)(W + i * 4);
    uint2 u;
    *(__half2*)&u.x = __floats2half2_rn(v.x, v.y);
    *(__half2*)&u.y = __floats2half2_rn(v.z, v.w);
    *(uint2*)(Wh + i * 4) = u;
}

// ---------------------------------------------------------------------------
// CSR build: zero -> count(+slot) -> 3-phase scan -> atomic-free fill
// ---------------------------------------------------------------------------
__global__ void zero2_kernel(int* a, int* b, int n) {
    int i = blockIdx.x * blockDim.x + threadIdx.x;
    if (i < n) { a[i] = 0; b[i] = 0; }
}

__global__ void count_slot_kernel(const int* __restrict__ dstZ, const int* __restrict__ dstA,
                                  int* __restrict__ cntZ, int* __restrict__ cntA,
                                  int* __restrict__ slotZ, int* __restrict__ slotA, int E) {
    int e = blockIdx.x * blockDim.x + threadIdx.x;
    if (e < E) {
        slotZ[e] = atomicAdd(&cntZ[dstZ[e]], 1);
        slotA[e] = atomicAdd(&cntA[dstA[e]], 1);
    }
}

__global__ __launch_bounds__(SCB) void block_sum_kernel(
    const int* __restrict__ cntZ, const int* __restrict__ cntA,
    int* __restrict__ partZ, int* __restrict__ partA, int n, int nblk)
{
    int b = blockIdx.x;
    const int* cnt = (b < nblk) ? cntZ : cntA;
    int*       prt = (b < nblk) ? partZ : partA;
    int bb = (b < nblk) ? b : b - nblk;
    int i = bb * SCB + threadIdx.x;
    int v = (i < n) ? cnt[i] : 0;
    #pragma unroll
    for (int d = 16; d; d >>= 1) v += __shfl_xor_sync(0xffffffffu, v, d);
    __shared__ int ws[SCB / 32];
    int lane = threadIdx.x & 31, w = threadIdx.x >> 5;
    if (lane == 0) ws[w] = v;
    __syncthreads();
    if (threadIdx.x < SCB / 32) {
        int s = ws[threadIdx.x];
        #pragma unroll
        for (int d = (SCB / 64); d; d >>= 1) s += __shfl_xor_sync((1u << (SCB / 32)) - 1u, s, d);
        if (threadIdx.x == 0) prt[bb] = s;
    }
}

__global__ __launch_bounds__(512) void scan_partials_kernel(
    int* __restrict__ partZ, int* __restrict__ partA, int nblk)
{
    int* part = blockIdx.x ? partA : partZ;
    int t = threadIdx.x;
    __shared__ int sm[512];
    int v = (t < nblk) ? part[t] : 0;
    sm[t] = v;
    __syncthreads();
    #pragma unroll
    for (int d = 1; d < 512; d <<= 1) {
        int u = (t >= d) ? sm[t - d] : 0;
        __syncthreads();
        sm[t] += u;
        __syncthreads();
    }
    if (t < nblk) part[t] = sm[t] - v;   // exclusive
}

__global__ __launch_bounds__(SCB) void scan_write_kernel(
    const int* __restrict__ cntZ, const int* __restrict__ partZ, int* __restrict__ rpZ,
    const int* __restrict__ cntA, const int* __restrict__ partA, int* __restrict__ rpA,
    int n, int nblk)
{
    int b = blockIdx.x;
    const int* cnt  = (b < nblk) ? cntZ : cntA;
    const int* prt  = (b < nblk) ? partZ : partA;
    int*       rp   = (b < nblk) ? rpZ : rpA;
    int bb = (b < nblk) ? b : b - nblk;
    int t = threadIdx.x;
    int i = bb * SCB + t;
    int v = (i < n) ? cnt[i] : 0;
    int lane = t & 31, w = t >> 5;
    int inc = v;
    #pragma unroll
    for (int d = 1; d < 32; d <<= 1) {
        int u = __shfl_up_sync(0xffffffffu, inc, d);
        if (lane >= d) inc += u;
    }
    __shared__ int wsum[SCB / 32];
    if (lane == 31) wsum[w] = inc;
    __syncthreads();
    if (t < SCB / 32) {
        int s = wsum[t];
        int sc = s;
        #pragma unroll
        for (int d = 1; d < SCB / 32; d <<= 1) {
            int u = __shfl_up_sync((1u << (SCB / 32)) - 1u, sc, d);
            if (t >= d) sc += u;
        }
        wsum[t] = sc - s;   // exclusive warp offset
    }
    __syncthreads();
    int excl = inc - v + wsum[w] + prt[bb];
    if (i < n) rp[i] = excl;
    if (i == n - 1) rp[n] = excl + v;
}

__global__ void fill_both_kernel(
    const int* __restrict__ srcZ, const int* __restrict__ dstZ, const float* __restrict__ valsZ,
    const int* __restrict__ srcA, const int* __restrict__ dstA, const float* __restrict__ valsA,
    const int* __restrict__ rpZ, const int* __restrict__ rpA,
    const int* __restrict__ slotZ, const int* __restrict__ slotA,
    int2* __restrict__ edgeZ, int2* __restrict__ edgeA, int E)
{
    int e = blockIdx.x * blockDim.x + threadIdx.x;
    if (e >= E) return;
    {
        int pos = __ldg(&rpZ[dstZ[e]]) + slotZ[e];
        edgeZ[pos] = make_int2(srcZ[e], __float_as_int(valsZ[e]));
    }
    {
        int pos = __ldg(&rpA[dstA[e]]) + slotA[e];
        edgeA[pos] = make_int2(srcA[e], __float_as_int(valsA[e]));
    }
}

// ---------------------------------------------------------------------------
// Gather SpMM (128-wide, fp16 in/out): warp per node, lane owns 4 features.
// Edges batch-loaded coalesced (32/warp) and shfl-broadcast to all lanes.
// ---------------------------------------------------------------------------
__global__ __launch_bounds__(256) void spmm_gather128h(
    const __half* __restrict__ X, const int2* __restrict__ edges,
    const int* __restrict__ rp, __half* __restrict__ Y, int n)
{
    int w = (blockIdx.x * 256 + (int)threadIdx.x) >> 5;
    if (w >= n) return;
    int lane = threadIdx.x & 31;
    int beg = rp[w], end = rp[w + 1];
    float4 acc = make_float4(0.f, 0.f, 0.f, 0.f);
    for (int base = beg; base < end; base += 32) {
        int m = end - base;
        if (m > 32) m = 32;
        int2 e = (lane < m) ? edges[base + lane] : make_int2(0, 0);
        #pragma unroll 4
        for (int k = 0; k < m; k++) {
            int   s = __shfl_sync(0xffffffffu, e.x, k);
            float v = __int_as_float(__shfl_sync(0xffffffffu, e.y, k));
            uint2 u = *(const uint2*)(X + (size_t)s * NF + lane * 4);
            float2 f0 = __half22float2(*(__half2*)&u.x);
            float2 f1 = __half22float2(*(__half2*)&u.y);
            acc.x += v * f0.x; acc.y += v * f0.y;
            acc.z += v * f1.x; acc.w += v * f1.y;
        }
    }
    uint2 o;
    *(__half2*)&o.x = __floats2half2_rn(acc.x, acc.y);
    *(__half2*)&o.y = __floats2half2_rn(acc.z, acc.w);
    *(uint2*)(Y + (size_t)w * NF + lane * 4) = o;
}

// ---------------------------------------------------------------------------
// Fused gather SpMM (40-wide, fp16) + bias + log_softmax.
// TWO nodes per warp: 16-lane groups, lanes 0..9 of each group own 4 classes.
// ---------------------------------------------------------------------------
__global__ __launch_bounds__(256) void spmm40_lsm_kernel(
    const __half* __restrict__ T, const int2* __restrict__ edges,
    const int* __restrict__ rp, const float* __restrict__ b2,
    float* __restrict__ out, int n)
{
    int w    = (blockIdx.x * 256 + (int)threadIdx.x) >> 5;
    int lane = threadIdx.x & 31;
    int grp  = lane >> 4;      // 0 or 1
    int l    = lane & 15;      // 0..15
    int node = w * 2 + grp;
    bool act = (l < 10) && (node < n);

    float4 acc = make_float4(0.f, 0.f, 0.f, 0.f);
    if (act) {
        int beg = rp[node], end = rp[node + 1];
        #pragma unroll 4
        for (int j = beg; j < end; j++) {
            int2 e = edges[j];
            float v = __int_as_float(e.y);
            uint2 u = *(const uint2*)(T + (size_t)e.x * NCLS + l * 4);
            float2 f0 = __half22float2(*(__half2*)&u.x);
            float2 f1 = __half22float2(*(__half2*)&u.y);
            acc.x += v * f0.x; acc.y += v * f0.y;
            acc.z += v * f1.x; acc.w += v * f1.y;
        }
        float4 bv = *(const float4*)(b2 + l * 4);
        acc.x += bv.x; acc.y += bv.y; acc.z += bv.z; acc.w += bv.w;
    }
    float m = act ? fmaxf(fmaxf(acc.x, acc.y), fmaxf(acc.z, acc.w)) : -INFINITY;
    #pragma unroll
    for (int d = 8; d; d >>= 1) m = fmaxf(m, __shfl_xor_sync(0xffffffffu, m, d, 16));
    float e = act ? (__expf(acc.x - m) + __expf(acc.y - m) +
                     __expf(acc.z - m) + __expf(acc.w - m)) : 0.f;
    #pragma unroll
    for (int d = 8; d; d >>= 1) e += __shfl_xor_sync(0xffffffffu, e, d, 16);
    float lse = logf(e) + m;
    if (act) {
        float4 o = make_float4(acc.x - lse, acc.y - lse, acc.z - lse, acc.w - lse);
        *(float4*)(out + (size_t)node * NCLS + l * 4) = o;
    }
}

// ---------------------------------------------------------------------------
// TF32 MMA GEMM (fp16 input AND fp16 weights) + bias + BN + ReLU -> fp16.
// 256 thr = 8 warps (2 warp_m x 4 warp_n). Tile 64 x 128. Pitch-36 smem.
// ---------------------------------------------------------------------------
#define PK 36

__device__ __forceinline__ void mma_tf32(float* c, const unsigned* a, unsigned b0, unsigned b1) {
    asm volatile(
        "mma.sync.aligned.m16n8k8.row.col.f32.tf32.tf32.f32 "
        "{%0,%1,%2,%3}, {%4,%5,%6,%7}, {%8,%9}, {%0,%1,%2,%3};"
        : "+f"(c[0]), "+f"(c[1]), "+f"(c[2]), "+f"(c[3])
        : "r"(a[0]), "r"(a[1]), "r"(a[2]), "r"(a[3]), "r"(b0), "r"(b1));
}

__device__ __forceinline__ void h4_to_tf32(uint2 u, float* p) {
    float2 f0 = __half22float2(*(__half2*)&u.x);
    float2 f1 = __half22float2(*(__half2*)&u.y);
    p[0] = __uint_as_float(f2tf32(f0.x));
    p[1] = __uint_as_float(f2tf32(f0.y));
    p[2] = __uint_as_float(f2tf32(f1.x));
    p[3] = __uint_as_float(f2tf32(f1.y));
}

__global__ __launch_bounds__(256) void gemm_bn_relu_mma(
    const __half* __restrict__ Xh, const __half* __restrict__ Wh,
    const float* __restrict__ bias, const float* __restrict__ gamma,
    const float* __restrict__ beta, const float* __restrict__ rmean,
    const float* __restrict__ rvar, const float* __restrict__ am,
    __half* __restrict__ Y, int n)
{
    __shared__ float Xs[64][PK];
    __shared__ float Ws[128][PK];
    __shared__ float s_sc[128], s_sh[128], s_bs[128];

    int tid  = threadIdx.x;
    int lane = tid & 31;
    int wid  = tid >> 5;
    int warp_m = wid & 1;
    int warp_n = wid >> 1;
    int m0 = blockIdx.x * 64;

    if (tid < 128) {
        float s = gamma[tid] * rsqrtf(rvar[tid] + 1e-5f);
        s_sc[tid] = s;
        s_sh[tid] = beta[tid] - rmean[tid] * s;
        s_bs[tid] = bias[tid];
    }

    float acc[2][4][4];
    #pragma unroll
    for (int i = 0; i < 2; i++)
        #pragma unroll
        for (int j = 0; j < 4; j++)
            #pragma unroll
            for (int q = 0; q < 4; q++) acc[i][j][q] = 0.f;

    int g = lane >> 2, t = lane & 3;

    for (int k0 = 0; k0 < NF; k0 += 32) {
        #pragma unroll
        for (int q = 0; q < 2; q++) {
            int idx = tid * 2 + q;
            int r   = idx >> 3;
            int kc  = (idx & 7) * 4;
            uint2 u = make_uint2(0u, 0u);
            int gr = m0 + r;
            if (gr < n) u = *(const uint2*)(Xh + (size_t)gr * NF + k0 + kc);
            h4_to_tf32(u, &Xs[r][kc]);
        }
        #pragma unroll
        for (int q = 0; q < 4; q++) {
            int idx = tid * 4 + q;
            int o   = idx >> 3;
            int kc  = (idx & 7) * 4;
            uint2 u = *(const uint2*)(Wh + o * NF + k0 + kc);
            h4_to_tf32(u, &Ws[o][kc]);
        }
        __syncthreads();

        #pragma unroll
        for (int ks = 0; ks < 32; ks += 8) {
            unsigned a[2][4];
            #pragma unroll
            for (int ma = 0; ma < 2; ma++) {
                int rb = warp_m * 32 + ma * 16;
                a[ma][0] = __float_as_uint(Xs[rb + g    ][ks + t    ]);
                a[ma][1] = __float_as_uint(Xs[rb + g + 8][ks + t    ]);
                a[ma][2] = __float_as_uint(Xs[rb + g    ][ks + t + 4]);
                a[ma][3] = __float_as_uint(Xs[rb + g + 8][ks + t + 4]);
            }
            #pragma unroll
            for (int na = 0; na < 4; na++) {
                int nb = warp_n * 32 + na * 8;
                unsigned b0 = __float_as_uint(Ws[nb + g][ks + t    ]);
                unsigned b1 = __float_as_uint(Ws[nb + g][ks + t + 4]);
                mma_tf32(acc[0][na], a[0], b0, b1);
                mma_tf32(acc[1][na], a[1], b0, b1);
            }
        }
        __syncthreads();
    }

    #pragma unroll
    for (int ma = 0; ma < 2; ma++) {
        int r0 = m0 + warp_m * 32 + ma * 16 + g;
        int r1 = r0 + 8;
        float a0 = 1.f, a1 = 1.f;
        if (am != nullptr) {
            if (r0 < n) a0 = am[r0];
            if (r1 < n) a1 = am[r1];
        }
        #pragma unroll
        for (int na = 0; na < 4; na++) {
            int c = warp_n * 32 + na * 8 + 2 * t;
            float sc0 = s_sc[c], sc1 = s_sc[c + 1];
            float sh0 = s_sh[c], sh1 = s_sh[c + 1];
            float bs0 = s_bs[c], bs1 = s_bs[c + 1];
            if (r0 < n) {
                float ox = fmaxf((acc[ma][na][0] * a0 + bs0) * sc0 + sh0, 0.f);
                float oy = fmaxf((acc[ma][na][1] * a0 + bs1) * sc1 + sh1, 0.f);
                *(__half2*)(Y + (size_t)r0 * NF + c) = __floats2half2_rn(ox, oy);
            }
            if (r1 < n) {
                float ox = fmaxf((acc[ma][na][2] * a1 + bs0) * sc0 + sh0, 0.f);
                float oy = fmaxf((acc[ma][na][3] * a1 + bs1) * sc1 + sh1, 0.f);
                *(__half2*)(Y + (size_t)r1 * NF + c) = __floats2half2_rn(ox, oy);
            }
        }
    }
}

// ---------------------------------------------------------------------------
// TF32 MMA: t = h1 @ W2^T (N x 40), fp16 input/weights/output.
// ---------------------------------------------------------------------------
__global__ __launch_bounds__(256) void tgemm_mma(
    const __half* __restrict__ Xh, const __half* __restrict__ W2h,
    __half* __restrict__ T, int n)
{
    __shared__ float Xs[128][PK];
    __shared__ float Ws[NCLS][PK];

    int tid  = threadIdx.x;
    int lane = tid & 31;
    int wid  = tid >> 5;
    int m0 = blockIdx.x * 128;
    int g = lane >> 2, t = lane & 3;

    float acc[5][4];
    #pragma unroll
    for (int i = 0; i < 5; i++)
        #pragma unroll
        for (int q = 0; q < 4; q++) acc[i][q] = 0.f;

    for (int k0 = 0; k0 < NF; k0 += 32) {
        #pragma unroll
        for (int q = 0; q < 4; q++) {
            int idx = tid * 4 + q;
            int r   = idx >> 3;
            int kc  = (idx & 7) * 4;
            uint2 u = make_uint2(0u, 0u);
            int gr = m0 + r;
            if (gr < n) u = *(const uint2*)(Xh + (size_t)gr * NF + k0 + kc);
            h4_to_tf32(u, &Xs[r][kc]);
        }
        for (int idx = tid; idx < NCLS * 8; idx += 256) {
            int o  = idx >> 3;
            int kc = (idx & 7) * 4;
            uint2 u = *(const uint2*)(W2h + o * NF + k0 + kc);
            h4_to_tf32(u, &Ws[o][kc]);
        }
        __syncthreads();

        #pragma unroll
        for (int ks = 0; ks < 32; ks += 8) {
            int rb = wid * 16;
            unsigned a[4];
            a[0] = __float_as_uint(Xs[rb + g    ][ks + t    ]);
            a[1] = __float_as_uint(Xs[rb + g + 8][ks + t    ]);
            a[2] = __float_as_uint(Xs[rb + g    ][ks + t + 4]);
            a[3] = __float_as_uint(Xs[rb + g + 8][ks + t + 4]);
            #pragma unroll
            for (int na = 0; na < 5; na++) {
                unsigned b0 = __float_as_uint(Ws[na * 8 + g][ks + t    ]);
                unsigned b1 = __float_as_uint(Ws[na * 8 + g][ks + t + 4]);
                mma_tf32(acc[na], a, b0, b1);
            }
        }
        __syncthreads();
    }

    int r0 = m0 + wid * 16 + g;
    int r1 = r0 + 8;
    #pragma unroll
    for (int na = 0; na < 5; na++) {
        int c = na * 8 + 2 * t;
        if (r0 < n) *(__half2*)(T + (size_t)r0 * NCLS + c) = __floats2half2_rn(acc[na][0], acc[na][1]);
        if (r1 < n) *(__half2*)(T + (size_t)r1 * NCLS + c) = __floats2half2_rn(acc[na][2], acc[na][3]);
    }
}

// ---------------------------------------------------------------------------
// launch
// ---------------------------------------------------------------------------
extern "C" void kernel_launch(void* const* d_in, const int* in_sizes, int n_in,
                              void* d_out, int out_size)
{
    const float* x     = (const float*)d_in[0];
    const float* M     = (const float*)d_in[1];
    const float* AM    = (const float*)d_in[2];
    const int*   srcZ  = (const int*)  d_in[3];
    const int*   dstZ  = (const int*)  d_in[4];
    const float* valsZ = (const float*)d_in[5];
    const int*   src   = (const int*)  d_in[6];
    const int*   dst   = (const int*)  d_in[7];
    const float* vals  = (const float*)d_in[8];
    const float* W0  = (const float*)d_in[9];
    const float* b0  = (const float*)d_in[10];
    const float* g0  = (const float*)d_in[11];
    const float* be0 = (const float*)d_in[12];
    const float* rm0 = (const float*)d_in[13];
    const float* rv0 = (const float*)d_in[14];
    const float* W1  = (const float*)d_in[15];
    const float* b1  = (const float*)d_in[16];
    const float* g1  = (const float*)d_in[17];
    const float* be1 = (const float*)d_in[18];
    const float* rm1 = (const float*)d_in[19];
    const float* rv1 = (const float*)d_in[20];
    const float* W2  = (const float*)d_in[21];
    const float* b2  = (const float*)d_in[22];
    float* out = (float*)d_out;

    int n = in_sizes[1];
    int E = in_sizes[3];

    __half *hA, *hB, *t40h, *W0h, *W1h, *W2h;
    int *rpZ, *rpA, *cntZ, *cntA, *partZ, *partA, *slotZ, *slotA;
    int2 *edgeZ, *edgeA;
    cudaGetSymbolAddress((void**)&hA, g_hA);
    cudaGetSymbolAddress((void**)&hB, g_hB);
    cudaGetSymbolAddress((void**)&t40h, g_t40h);
    cudaGetSymbolAddress((void**)&W0h, g_W0h);
    cudaGetSymbolAddress((void**)&W1h, g_W1h);
    cudaGetSymbolAddress((void**)&W2h, g_W2h);
    cudaGetSymbolAddress((void**)&rpZ, g_rpZ);
    cudaGetSymbolAddress((void**)&rpA, g_rpA);
    cudaGetSymbolAddress((void**)&cntZ, g_cntZ);
    cudaGetSymbolAddress((void**)&cntA, g_cntA);
    cudaGetSymbolAddress((void**)&partZ, g_partZ);
    cudaGetSymbolAddress((void**)&partA, g_partA);
    cudaGetSymbolAddress((void**)&slotZ, g_slotZ);
    cudaGetSymbolAddress((void**)&slotA, g_slotA);
    cudaGetSymbolAddress((void**)&edgeZ, g_edgeZ);
    cudaGetSymbolAddress((void**)&edgeA, g_edgeA);

    int egrid   = (E + 255) / 256;
    int ngrid   = (n + 255) / 256;
    int nblk    = (n + SCB - 1) / SCB;
    int wgrid   = (n * 32 + 255) / 256;               // warp per node
    int w2grid  = (((n + 1) / 2) * 32 + 255) / 256;   // 2 nodes per warp
    int ggrid   = (n + 63) / 64;
    int tggrid  = (n + 127) / 128;
    int pgrid   = (n * 32 + 255) / 256;

    // --- CSR build + fp16 pre-passes ---
    zero2_kernel<<<ngrid, 256>>>(cntZ, cntA, n);
    mxhalf_kernel<<<pgrid, 256>>>(x, M, hA, n);
    w2h_kernel<<<(NF * NF / 4 + 255) / 256, 256>>>(W0, W0h, NF * NF / 4);
    w2h_kernel<<<(NF * NF / 4 + 255) / 256, 256>>>(W1, W1h, NF * NF / 4);
    w2h_kernel<<<(NCLS * NF / 4 + 255) / 256, 256>>>(W2, W2h, NCLS * NF / 4);
    count_slot_kernel<<<egrid, 256>>>(dstZ, dst, cntZ, cntA, slotZ, slotA, E);
    block_sum_kernel<<<2 * nblk, SCB>>>(cntZ, cntA, partZ, partA, n, nblk);
    scan_partials_kernel<<<2, 512>>>(partZ, partA, nblk);
    scan_write_kernel<<<2 * nblk, SCB>>>(cntZ, partZ, rpZ, cntA, partA, rpA, n, nblk);
    fill_both_kernel<<<egrid, 256>>>(srcZ, dstZ, valsZ, src, dst, vals,
                                     rpZ, rpA, slotZ, slotA, edgeZ, edgeA, E);

    // --- layer 0 ---
    spmm_gather128h<<<wgrid, 256>>>(hA, edgeZ, rpZ, hB, n);
    gemm_bn_relu_mma<<<ggrid, 256>>>(hB, W0h, b0, g0, be0, rm0, rv0, AM, hA, n);

    // --- layer 1 ---
    spmm_gather128h<<<wgrid, 256>>>(hA, edgeA, rpA, hB, n);
    gemm_bn_relu_mma<<<ggrid, 256>>>(hB, W1h, b1, g1, be1, rm1, rv1, nullptr, hA, n);

    // --- layer 2 (commuted) ---
    tgemm_mma<<<tggrid, 256>>>(hA, W2h, t40h, n);
    spmm40_lsm_kernel<<<w2grid, 256>>>(t40h, edgeA, rpA, b2, out, n);
}

// round 15
// speedup vs baseline: 1.0317x; 1.0317x over previous
#include <cuda_runtime.h>
#include <cuda_fp16.h>
#include <math.h>

#define NNODE 100000
#define NF 128
#define NCLS 40
#define EMAX 1600000
#define SCB 256   // scan block size

// ---------------------------------------------------------------------------
// Static device scratch
// ---------------------------------------------------------------------------
__device__ __half g_hA[(size_t)NNODE * NF];     // fp16 ping
__device__ __half g_hB[(size_t)NNODE * NF];     // fp16 pong
__device__ __half g_t40h[(size_t)NNODE * NCLS]; // fp16 t = h1 @ W2^T
__device__ __half g_W0h[NF * NF];
__device__ __half g_W1h[NF * NF];
__device__ __half g_W2h[NCLS * NF];
__device__ int    g_rpZ[NNODE + 1];
__device__ int    g_rpA[NNODE + 1];
__device__ int    g_cntZ[NNODE];
__device__ int    g_cntA[NNODE];
__device__ int    g_partZ[(NNODE + SCB - 1) / SCB];
__device__ int    g_partA[(NNODE + SCB - 1) / SCB];
__device__ int    g_slotP[EMAX];                // packed (slotZ<<16)|slotA
__device__ int2   g_edgeZ[EMAX];                // {src, val_bits} CSR-ordered
__device__ int2   g_edgeA[EMAX];

__device__ __forceinline__ unsigned f2tf32(float f) {
    unsigned u;
    asm("cvt.rna.tf32.f32 %0, %1;" : "=r"(u) : "f"(f));
    return u;
}

// ---------------------------------------------------------------------------
// Pre-pass: xh = half(M[row] * x)
// ---------------------------------------------------------------------------
__global__ __launch_bounds__(256) void mxhalf_kernel(
    const float* __restrict__ x, const float* __restrict__ M,
    __half* __restrict__ xh, int n)
{
    int i = blockIdx.x * blockDim.x + threadIdx.x;  // one thread per 4 elems
    if (i >= n * (NF / 4)) return;
    int row = i >> 5;
    int col = (i & 31) * 4;
    float m = M[row];
    float4 v = *(const float4*)(x + (size_t)row * NF + col);
    uint2 u;
    *(__half2*)&u.x = __floats2half2_rn(v.x * m, v.y * m);
    *(__half2*)&u.y = __floats2half2_rn(v.z * m, v.w * m);
    *(uint2*)(xh + (size_t)row * NF + col) = u;
}

// ---------------------------------------------------------------------------
// All three weights fp32 -> fp16 in ONE launch (fp16 mantissa == tf32
// mantissa; fp16->float exact, so effective rounding unchanged)
// ---------------------------------------------------------------------------
#define W0Q (NF * NF / 4)
#define W1Q (NF * NF / 4)
#define W2Q (NCLS * NF / 4)

__global__ void w2h_all_kernel(const float* __restrict__ W0, __half* __restrict__ W0h,
                               const float* __restrict__ W1, __half* __restrict__ W1h,
                               const float* __restrict__ W2, __half* __restrict__ W2h)
{
    int i = blockIdx.x * blockDim.x + threadIdx.x;
    const float* W;
    __half* Wh;
    int q;
    if (i < W0Q)                { W = W0; Wh = W0h; q = i; }
    else if (i < W0Q + W1Q)     { W = W1; Wh = W1h; q = i - W0Q; }
    else if (i < W0Q + W1Q + W2Q) { W = W2; Wh = W2h; q = i - W0Q - W1Q; }
    else return;
    float4 v = *(const float4*)(W + q * 4);
    uint2 u;
    *(__half2*)&u.x = __floats2half2_rn(v.x, v.y);
    *(__half2*)&u.y = __floats2half2_rn(v.z, v.w);
    *(uint2*)(Wh + q * 4) = u;
}

// ---------------------------------------------------------------------------
// CSR build: zero -> count(+packed slot) -> 3-phase scan -> atomic-free fill
// ---------------------------------------------------------------------------
__global__ void zero2_kernel(int* a, int* b, int n) {
    int i = blockIdx.x * blockDim.x + threadIdx.x;
    if (i < n) { a[i] = 0; b[i] = 0; }
}

__global__ void count_slot_kernel(const int* __restrict__ dstZ, const int* __restrict__ dstA,
                                  int* __restrict__ cntZ, int* __restrict__ cntA,
                                  int* __restrict__ slotP, int E) {
    int e = blockIdx.x * blockDim.x + threadIdx.x;
    if (e < E) {
        int sZ = atomicAdd(&cntZ[dstZ[e]], 1);
        int sA = atomicAdd(&cntA[dstA[e]], 1);
        slotP[e] = (sZ << 16) | sA;
    }
}

__global__ __launch_bounds__(SCB) void block_sum_kernel(
    const int* __restrict__ cntZ, const int* __restrict__ cntA,
    int* __restrict__ partZ, int* __restrict__ partA, int n, int nblk)
{
    int b = blockIdx.x;
    const int* cnt = (b < nblk) ? cntZ : cntA;
    int*       prt = (b < nblk) ? partZ : partA;
    int bb = (b < nblk) ? b : b - nblk;
    int i = bb * SCB + threadIdx.x;
    int v = (i < n) ? cnt[i] : 0;
    #pragma unroll
    for (int d = 16; d; d >>= 1) v += __shfl_xor_sync(0xffffffffu, v, d);
    __shared__ int ws[SCB / 32];
    int lane = threadIdx.x & 31, w = threadIdx.x >> 5;
    if (lane == 0) ws[w] = v;
    __syncthreads();
    if (threadIdx.x < SCB / 32) {
        int s = ws[threadIdx.x];
        #pragma unroll
        for (int d = (SCB / 64); d; d >>= 1) s += __shfl_xor_sync((1u << (SCB / 32)) - 1u, s, d);
        if (threadIdx.x == 0) prt[bb] = s;
    }
}

__global__ __launch_bounds__(512) void scan_partials_kernel(
    int* __restrict__ partZ, int* __restrict__ partA, int nblk)
{
    int* part = blockIdx.x ? partA : partZ;
    int t = threadIdx.x;
    __shared__ int sm[512];
    int v = (t < nblk) ? part[t] : 0;
    sm[t] = v;
    __syncthreads();
    #pragma unroll
    for (int d = 1; d < 512; d <<= 1) {
        int u = (t >= d) ? sm[t - d] : 0;
        __syncthreads();
        sm[t] += u;
        __syncthreads();
    }
    if (t < nblk) part[t] = sm[t] - v;   // exclusive
}

__global__ __launch_bounds__(SCB) void scan_write_kernel(
    const int* __restrict__ cntZ, const int* __restrict__ partZ, int* __restrict__ rpZ,
    const int* __restrict__ cntA, const int* __restrict__ partA, int* __restrict__ rpA,
    int n, int nblk)
{
    int b = blockIdx.x;
    const int* cnt  = (b < nblk) ? cntZ : cntA;
    const int* prt  = (b < nblk) ? partZ : partA;
    int*       rp   = (b < nblk) ? rpZ : rpA;
    int bb = (b < nblk) ? b : b - nblk;
    int t = threadIdx.x;
    int i = bb * SCB + t;
    int v = (i < n) ? cnt[i] : 0;
    int lane = t & 31, w = t >> 5;
    int inc = v;
    #pragma unroll
    for (int d = 1; d < 32; d <<= 1) {
        int u = __shfl_up_sync(0xffffffffu, inc, d);
        if (lane >= d) inc += u;
    }
    __shared__ int wsum[SCB / 32];
    if (lane == 31) wsum[w] = inc;
    __syncthreads();
    if (t < SCB / 32) {
        int s = wsum[t];
        int sc = s;
        #pragma unroll
        for (int d = 1; d < SCB / 32; d <<= 1) {
            int u = __shfl_up_sync((1u << (SCB / 32)) - 1u, sc, d);
            if (t >= d) sc += u;
        }
        wsum[t] = sc - s;   // exclusive warp offset
    }
    __syncthreads();
    int excl = inc - v + wsum[w] + prt[bb];
    if (i < n) rp[i] = excl;
    if (i == n - 1) rp[n] = excl + v;
}

// atomic-free fill: pos = rp[dst] + slot
__global__ void fill_both_kernel(
    const int* __restrict__ srcZ, const int* __restrict__ dstZ, const float* __restrict__ valsZ,
    const int* __restrict__ srcA, const int* __restrict__ dstA, const float* __restrict__ valsA,
    const int* __restrict__ rpZ, const int* __restrict__ rpA,
    const int* __restrict__ slotP,
    int2* __restrict__ edgeZ, int2* __restrict__ edgeA, int E)
{
    int e = blockIdx.x * blockDim.x + threadIdx.x;
    if (e >= E) return;
    int sp = slotP[e];
    {
        int pos = __ldg(&rpZ[dstZ[e]]) + (sp >> 16);
        edgeZ[pos] = make_int2(srcZ[e], __float_as_int(valsZ[e]));
    }
    {
        int pos = __ldg(&rpA[dstA[e]]) + (sp & 0xffff);
        edgeA[pos] = make_int2(srcA[e], __float_as_int(valsA[e]));
    }
}

// ---------------------------------------------------------------------------
// Gather SpMM (128-wide, fp16 in/out): warp per node, lane owns 4 features.
// [R13-proven: sequential broadcast edge loads are L1-resident]
// ---------------------------------------------------------------------------
__global__ __launch_bounds__(256) void spmm_gather128h(
    const __half* __restrict__ X, const int2* __restrict__ edges,
    const int* __restrict__ rp, __half* __restrict__ Y, int n)
{
    int w = (blockIdx.x * 256 + (int)threadIdx.x) >> 5;
    if (w >= n) return;
    int lane = threadIdx.x & 31;
    int beg = rp[w], end = rp[w + 1];
    float4 acc = make_float4(0.f, 0.f, 0.f, 0.f);
    #pragma unroll 4
    for (int j = beg; j < end; j++) {
        int2 e = edges[j];
        float v = __int_as_float(e.y);
        uint2 u = *(const uint2*)(X + (size_t)e.x * NF + lane * 4);
        float2 f0 = __half22float2(*(__half2*)&u.x);
        float2 f1 = __half22float2(*(__half2*)&u.y);
        acc.x += v * f0.x; acc.y += v * f0.y;
        acc.z += v * f1.x; acc.w += v * f1.y;
    }
    uint2 o;
    *(__half2*)&o.x = __floats2half2_rn(acc.x, acc.y);
    *(__half2*)&o.y = __floats2half2_rn(acc.z, acc.w);
    *(uint2*)(Y + (size_t)w * NF + lane * 4) = o;
}

// ---------------------------------------------------------------------------
// Fused gather SpMM (40-wide, fp16) + bias + log_softmax.
// TWO nodes per warp: 16-lane groups, lanes 0..9 of each group own 4 classes.
// ---------------------------------------------------------------------------
__global__ __launch_bounds__(256) void spmm40_lsm_kernel(
    const __half* __restrict__ T, const int2* __restrict__ edges,
    const int* __restrict__ rp, const float* __restrict__ b2,
    float* __restrict__ out, int n)
{
    int w    = (blockIdx.x * 256 + (int)threadIdx.x) >> 5;
    int lane = threadIdx.x & 31;
    int grp  = lane >> 4;      // 0 or 1
    int l    = lane & 15;      // 0..15
    int node = w * 2 + grp;
    bool act = (l < 10) && (node < n);

    float4 acc = make_float4(0.f, 0.f, 0.f, 0.f);
    if (act) {
        int beg = rp[node], end = rp[node + 1];
        #pragma unroll 4
        for (int j = beg; j < end; j++) {
            int2 e = edges[j];
            float v = __int_as_float(e.y);
            uint2 u = *(const uint2*)(T + (size_t)e.x * NCLS + l * 4);
            float2 f0 = __half22float2(*(__half2*)&u.x);
            float2 f1 = __half22float2(*(__half2*)&u.y);
            acc.x += v * f0.x; acc.y += v * f0.y;
            acc.z += v * f1.x; acc.w += v * f1.y;
        }
        float4 bv = *(const float4*)(b2 + l * 4);
        acc.x += bv.x; acc.y += bv.y; acc.z += bv.z; acc.w += bv.w;
    }
    float m = act ? fmaxf(fmaxf(acc.x, acc.y), fmaxf(acc.z, acc.w)) : -INFINITY;
    #pragma unroll
    for (int d = 8; d; d >>= 1) m = fmaxf(m, __shfl_xor_sync(0xffffffffu, m, d, 16));
    float e = act ? (__expf(acc.x - m) + __expf(acc.y - m) +
                     __expf(acc.z - m) + __expf(acc.w - m)) : 0.f;
    #pragma unroll
    for (int d = 8; d; d >>= 1) e += __shfl_xor_sync(0xffffffffu, e, d, 16);
    float lse = logf(e) + m;
    if (act) {
        float4 o = make_float4(acc.x - lse, acc.y - lse, acc.z - lse, acc.w - lse);
        *(float4*)(out + (size_t)node * NCLS + l * 4) = o;
    }
}

// ---------------------------------------------------------------------------
// TF32 MMA GEMM (fp16 input AND fp16 weights) + bias + BN + ReLU -> fp16.
// 256 thr = 8 warps (2 warp_m x 4 warp_n). Tile 64 x 128. Pitch-36 smem.
// ---------------------------------------------------------------------------
#define PK 36

__device__ __forceinline__ void mma_tf32(float* c, const unsigned* a, unsigned b0, unsigned b1) {
    asm volatile(
        "mma.sync.aligned.m16n8k8.row.col.f32.tf32.tf32.f32 "
        "{%0,%1,%2,%3}, {%4,%5,%6,%7}, {%8,%9}, {%0,%1,%2,%3};"
        : "+f"(c[0]), "+f"(c[1]), "+f"(c[2]), "+f"(c[3])
        : "r"(a[0]), "r"(a[1]), "r"(a[2]), "r"(a[3]), "r"(b0), "r"(b1));
}

__device__ __forceinline__ void h4_to_tf32(uint2 u, float* p) {
    float2 f0 = __half22float2(*(__half2*)&u.x);
    float2 f1 = __half22float2(*(__half2*)&u.y);
    p[0] = __uint_as_float(f2tf32(f0.x));
    p[1] = __uint_as_float(f2tf32(f0.y));
    p[2] = __uint_as_float(f2tf32(f1.x));
    p[3] = __uint_as_float(f2tf32(f1.y));
}

__global__ __launch_bounds__(256) void gemm_bn_relu_mma(
    const __half* __restrict__ Xh, const __half* __restrict__ Wh,
    const float* __restrict__ bias, const float* __restrict__ gamma,
    const float* __restrict__ beta, const float* __restrict__ rmean,
    const float* __restrict__ rvar, const float* __restrict__ am,
    __half* __restrict__ Y, int n)
{
    __shared__ float Xs[64][PK];
    __shared__ float Ws[128][PK];
    __shared__ float s_sc[128], s_sh[128], s_bs[128];

    int tid  = threadIdx.x;
    int lane = tid & 31;
    int wid  = tid >> 5;
    int warp_m = wid & 1;
    int warp_n = wid >> 1;
    int m0 = blockIdx.x * 64;

    if (tid < 128) {
        float s = gamma[tid] * rsqrtf(rvar[tid] + 1e-5f);
        s_sc[tid] = s;
        s_sh[tid] = beta[tid] - rmean[tid] * s;
        s_bs[tid] = bias[tid];
    }

    float acc[2][4][4];
    #pragma unroll
    for (int i = 0; i < 2; i++)
        #pragma unroll
        for (int j = 0; j < 4; j++)
            #pragma unroll
            for (int q = 0; q < 4; q++) acc[i][j][q] = 0.f;

    int g = lane >> 2, t = lane & 3;

    for (int k0 = 0; k0 < NF; k0 += 32) {
        #pragma unroll
        for (int q = 0; q < 2; q++) {
            int idx = tid * 2 + q;
            int r   = idx >> 3;
            int kc  = (idx & 7) * 4;
            uint2 u = make_uint2(0u, 0u);
            int gr = m0 + r;
            if (gr < n) u = *(const uint2*)(Xh + (size_t)gr * NF + k0 + kc);
            h4_to_tf32(u, &Xs[r][kc]);
        }
        #pragma unroll
        for (int q = 0; q < 4; q++) {
            int idx = tid * 4 + q;
            int o   = idx >> 3;
            int kc  = (idx & 7) * 4;
            uint2 u = *(const uint2*)(Wh + o * NF + k0 + kc);
            h4_to_tf32(u, &Ws[o][kc]);
        }
        __syncthreads();

        #pragma unroll
        for (int ks = 0; ks < 32; ks += 8) {
            unsigned a[2][4];
            #pragma unroll
            for (int ma = 0; ma < 2; ma++) {
                int rb = warp_m * 32 + ma * 16;
                a[ma][0] = __float_as_uint(Xs[rb + g    ][ks + t    ]);
                a[ma][1] = __float_as_uint(Xs[rb + g + 8][ks + t    ]);
                a[ma][2] = __float_as_uint(Xs[rb + g    ][ks + t + 4]);
                a[ma][3] = __float_as_uint(Xs[rb + g + 8][ks + t + 4]);
            }
            #pragma unroll
            for (int na = 0; na < 4; na++) {
                int nb = warp_n * 32 + na * 8;
                unsigned b0 = __float_as_uint(Ws[nb + g][ks + t    ]);
                unsigned b1 = __float_as_uint(Ws[nb + g][ks + t + 4]);
                mma_tf32(acc[0][na], a[0], b0, b1);
                mma_tf32(acc[1][na], a[1], b0, b1);
            }
        }
        __syncthreads();
    }

    #pragma unroll
    for (int ma = 0; ma < 2; ma++) {
        int r0 = m0 + warp_m * 32 + ma * 16 + g;
        int r1 = r0 + 8;
        float a0 = 1.f, a1 = 1.f;
        if (am != nullptr) {
            if (r0 < n) a0 = am[r0];
            if (r1 < n) a1 = am[r1];
        }
        #pragma unroll
        for (int na = 0; na < 4; na++) {
            int c = warp_n * 32 + na * 8 + 2 * t;
            float sc0 = s_sc[c], sc1 = s_sc[c + 1];
            float sh0 = s_sh[c], sh1 = s_sh[c + 1];
            float bs0 = s_bs[c], bs1 = s_bs[c + 1];
            if (r0 < n) {
                float ox = fmaxf((acc[ma][na][0] * a0 + bs0) * sc0 + sh0, 0.f);
                float oy = fmaxf((acc[ma][na][1] * a0 + bs1) * sc1 + sh1, 0.f);
                *(__half2*)(Y + (size_t)r0 * NF + c) = __floats2half2_rn(ox, oy);
            }
            if (r1 < n) {
                float ox = fmaxf((acc[ma][na][2] * a1 + bs0) * sc0 + sh0, 0.f);
                float oy = fmaxf((acc[ma][na][3] * a1 + bs1) * sc1 + sh1, 0.f);
                *(__half2*)(Y + (size_t)r1 * NF + c) = __floats2half2_rn(ox, oy);
            }
        }
    }
}

// ---------------------------------------------------------------------------
// TF32 MMA: t = h1 @ W2^T (N x 40), fp16 input/weights/output.
// ---------------------------------------------------------------------------
__global__ __launch_bounds__(256) void tgemm_mma(
    const __half* __restrict__ Xh, const __half* __restrict__ W2h,
    __half* __restrict__ T, int n)
{
    __shared__ float Xs[128][PK];
    __shared__ float Ws[NCLS][PK];

    int tid  = threadIdx.x;
    int lane = tid & 31;
    int wid  = tid >> 5;
    int m0 = blockIdx.x * 128;
    int g = lane >> 2, t = lane & 3;

    float acc[5][4];
    #pragma unroll
    for (int i = 0; i < 5; i++)
        #pragma unroll
        for (int q = 0; q < 4; q++) acc[i][q] = 0.f;

    for (int k0 = 0; k0 < NF; k0 += 32) {
        #pragma unroll
        for (int q = 0; q < 4; q++) {
            int idx = tid * 4 + q;
            int r   = idx >> 3;
            int kc  = (idx & 7) * 4;
            uint2 u = make_uint2(0u, 0u);
            int gr = m0 + r;
            if (gr < n) u = *(const uint2*)(Xh + (size_t)gr * NF + k0 + kc);
            h4_to_tf32(u, &Xs[r][kc]);
        }
        for (int idx = tid; idx < NCLS * 8; idx += 256) {
            int o  = idx >> 3;
            int kc = (idx & 7) * 4;
            uint2 u = *(const uint2*)(W2h + o * NF + k0 + kc);
            h4_to_tf32(u, &Ws[o][kc]);
        }
        __syncthreads();

        #pragma unroll
        for (int ks = 0; ks < 32; ks += 8) {
            int rb = wid * 16;
            unsigned a[4];
            a[0] = __float_as_uint(Xs[rb + g    ][ks + t    ]);
            a[1] = __float_as_uint(Xs[rb + g + 8][ks + t    ]);
            a[2] = __float_as_uint(Xs[rb + g    ][ks + t + 4]);
            a[3] = __float_as_uint(Xs[rb + g + 8][ks + t + 4]);
            #pragma unroll
            for (int na = 0; na < 5; na++) {
                unsigned b0 = __float_as_uint(Ws[na * 8 + g][ks + t    ]);
                unsigned b1 = __float_as_uint(Ws[na * 8 + g][ks + t + 4]);
                mma_tf32(acc[na], a, b0, b1);
            }
        }
        __syncthreads();
    }

    int r0 = m0 + wid * 16 + g;
    int r1 = r0 + 8;
    #pragma unroll
    for (int na = 0; na < 5; na++) {
        int c = na * 8 + 2 * t;
        if (r0 < n) *(__half2*)(T + (size_t)r0 * NCLS + c) = __floats2half2_rn(acc[na][0], acc[na][1]);
        if (r1 < n) *(__half2*)(T + (size_t)r1 * NCLS + c) = __floats2half2_rn(acc[na][2], acc[na][3]);
    }
}

// ---------------------------------------------------------------------------
// launch
// ---------------------------------------------------------------------------
extern "C" void kernel_launch(void* const* d_in, const int* in_sizes, int n_in,
                              void* d_out, int out_size)
{
    const float* x     = (const float*)d_in[0];
    const float* M     = (const float*)d_in[1];
    const float* AM    = (const float*)d_in[2];
    const int*   srcZ  = (const int*)  d_in[3];
    const int*   dstZ  = (const int*)  d_in[4];
    const float* valsZ = (const float*)d_in[5];
    const int*   src   = (const int*)  d_in[6];
    const int*   dst   = (const int*)  d_in[7];
    const float* vals  = (const float*)d_in[8];
    const float* W0  = (const float*)d_in[9];
    const float* b0  = (const float*)d_in[10];
    const float* g0  = (const float*)d_in[11];
    const float* be0 = (const float*)d_in[12];
    const float* rm0 = (const float*)d_in[13];
    const float* rv0 = (const float*)d_in[14];
    const float* W1  = (const float*)d_in[15];
    const float* b1  = (const float*)d_in[16];
    const float* g1  = (const float*)d_in[17];
    const float* be1 = (const float*)d_in[18];
    const float* rm1 = (const float*)d_in[19];
    const float* rv1 = (const float*)d_in[20];
    const float* W2  = (const float*)d_in[21];
    const float* b2  = (const float*)d_in[22];
    float* out = (float*)d_out;

    int n = in_sizes[1];
    int E = in_sizes[3];

    __half *hA, *hB, *t40h, *W0h, *W1h, *W2h;
    int *rpZ, *rpA, *cntZ, *cntA, *partZ, *partA, *slotP;
    int2 *edgeZ, *edgeA;
    cudaGetSymbolAddress((void**)&hA, g_hA);
    cudaGetSymbolAddress((void**)&hB, g_hB);
    cudaGetSymbolAddress((void**)&t40h, g_t40h);
    cudaGetSymbolAddress((void**)&W0h, g_W0h);
    cudaGetSymbolAddress((void**)&W1h, g_W1h);
    cudaGetSymbolAddress((void**)&W2h, g_W2h);
    cudaGetSymbolAddress((void**)&rpZ, g_rpZ);
    cudaGetSymbolAddress((void**)&rpA, g_rpA);
    cudaGetSymbolAddress((void**)&cntZ, g_cntZ);
    cudaGetSymbolAddress((void**)&cntA, g_cntA);
    cudaGetSymbolAddress((void**)&partZ, g_partZ);
    cudaGetSymbolAddress((void**)&partA, g_partA);
    cudaGetSymbolAddress((void**)&slotP, g_slotP);
    cudaGetSymbolAddress((void**)&edgeZ, g_edgeZ);
    cudaGetSymbolAddress((void**)&edgeA, g_edgeA);

    int egrid   = (E + 255) / 256;
    int ngrid   = (n + 255) / 256;
    int nblk    = (n + SCB - 1) / SCB;
    int wgrid   = (n * 32 + 255) / 256;               // warp per node
    int w2grid  = (((n + 1) / 2) * 32 + 255) / 256;   // 2 nodes per warp
    int ggrid   = (n + 63) / 64;
    int tggrid  = (n + 127) / 128;
    int pgrid   = (n * 32 + 255) / 256;
    int wq      = W0Q + W1Q + W2Q;

    // --- CSR build + fp16 pre-passes ---
    zero2_kernel<<<ngrid, 256>>>(cntZ, cntA, n);
    mxhalf_kernel<<<pgrid, 256>>>(x, M, hA, n);
    w2h_all_kernel<<<(wq + 255) / 256, 256>>>(W0, W0h, W1, W1h, W2, W2h);
    count_slot_kernel<<<egrid, 256>>>(dstZ, dst, cntZ, cntA, slotP, E);
    block_sum_kernel<<<2 * nblk, SCB>>>(cntZ, cntA, partZ, partA, n, nblk);
    scan_partials_kernel<<<2, 512>>>(partZ, partA, nblk);
    scan_write_kernel<<<2 * nblk, SCB>>>(cntZ, partZ, rpZ, cntA, partA, rpA, n, nblk);
    fill_both_kernel<<<egrid, 256>>>(srcZ, dstZ, valsZ, src, dst, vals,
                                     rpZ, rpA, slotP, edgeZ, edgeA, E);

    // --- layer 0 ---
    spmm_gather128h<<<wgrid, 256>>>(hA, edgeZ, rpZ, hB, n);
    gemm_bn_relu_mma<<<ggrid, 256>>>(hB, W0h, b0, g0, be0, rm0, rv0, AM, hA, n);

    // --- layer 1 ---
    spmm_gather128h<<<wgrid, 256>>>(hA, edgeA, rpA, hB, n);
    gemm_bn_relu_mma<<<ggrid, 256>>>(hB, W1h, b1, g1, be1, rm1, rv1, nullptr, hA, n);

    // --- layer 2 (commuted) ---
    tgemm_mma<<<tggrid, 256>>>(hA, W2h, t40h, n);
    spmm40_lsm_kernel<<<w2grid, 256>>>(t40h, edgeA, rpA, b2, out, n);
}

// round 16
// speedup vs baseline: 1.1683x; 1.1324x over previous
#include <cuda_runtime.h>
#include <cuda_fp16.h>
#include <math.h>

#define NNODE 100000
#define NF 128
#define NCLS 40
#define EMAX 1600000
#define SCB 256   // scan block size

// ---------------------------------------------------------------------------
// Static device scratch
// ---------------------------------------------------------------------------
__device__ __half g_hA[(size_t)NNODE * NF];     // fp16 ping
__device__ __half g_hB[(size_t)NNODE * NF];     // fp16 pong
__device__ __half g_t40h[(size_t)NNODE * NCLS]; // fp16 t = h1 @ W2^T
__device__ __half g_W0h[NF * NF];
__device__ __half g_W1h[NF * NF];
__device__ __half g_W2h[NCLS * NF];
__device__ int    g_rpZ[NNODE + 1];
__device__ int    g_rpA[NNODE + 1];
__device__ int    g_cntZ[NNODE];
__device__ int    g_cntA[NNODE];
__device__ int    g_partZ[(NNODE + SCB - 1) / SCB];
__device__ int    g_partA[(NNODE + SCB - 1) / SCB];
__device__ int    g_slotP[EMAX];                // packed (slotZ<<16)|slotA
__device__ int2   g_edgeZ[EMAX];                // {src, val_bits} CSR-ordered
__device__ int2   g_edgeA[EMAX];

// ---------------------------------------------------------------------------
// Pre-pass: xh = half(M[row] * x)
// ---------------------------------------------------------------------------
__global__ __launch_bounds__(256) void mxhalf_kernel(
    const float* __restrict__ x, const float* __restrict__ M,
    __half* __restrict__ xh, int n)
{
    int i = blockIdx.x * blockDim.x + threadIdx.x;  // one thread per 4 elems
    if (i >= n * (NF / 4)) return;
    int row = i >> 5;
    int col = (i & 31) * 4;
    float m = M[row];
    float4 v = *(const float4*)(x + (size_t)row * NF + col);
    uint2 u;
    *(__half2*)&u.x = __floats2half2_rn(v.x * m, v.y * m);
    *(__half2*)&u.y = __floats2half2_rn(v.z * m, v.w * m);
    *(uint2*)(xh + (size_t)row * NF + col) = u;
}

// ---------------------------------------------------------------------------
// All three weights fp32 -> fp16 in ONE launch
// ---------------------------------------------------------------------------
#define W0Q (NF * NF / 4)
#define W1Q (NF * NF / 4)
#define W2Q (NCLS * NF / 4)

__global__ void w2h_all_kernel(const float* __restrict__ W0, __half* __restrict__ W0h,
                               const float* __restrict__ W1, __half* __restrict__ W1h,
                               const float* __restrict__ W2, __half* __restrict__ W2h)
{
    int i = blockIdx.x * blockDim.x + threadIdx.x;
    const float* W;
    __half* Wh;
    int q;
    if (i < W0Q)                  { W = W0; Wh = W0h; q = i; }
    else if (i < W0Q + W1Q)       { W = W1; Wh = W1h; q = i - W0Q; }
    else if (i < W0Q + W1Q + W2Q) { W = W2; Wh = W2h; q = i - W0Q - W1Q; }
    else return;
    float4 v = *(const float4*)(W + q * 4);
    uint2 u;
    *(__half2*)&u.x = __floats2half2_rn(v.x, v.y);
    *(__half2*)&u.y = __floats2half2_rn(v.z, v.w);
    *(uint2*)(Wh + q * 4) = u;
}

// ---------------------------------------------------------------------------
// CSR build: zero -> count(+packed slot) -> 3-phase scan -> atomic-free fill
// ---------------------------------------------------------------------------
__global__ void zero2_kernel(int* a, int* b, int n) {
    int i = blockIdx.x * blockDim.x + threadIdx.x;
    if (i < n) { a[i] = 0; b[i] = 0; }
}

__global__ void count_slot_kernel(const int* __restrict__ dstZ, const int* __restrict__ dstA,
                                  int* __restrict__ cntZ, int* __restrict__ cntA,
                                  int* __restrict__ slotP, int E) {
    int e = blockIdx.x * blockDim.x + threadIdx.x;
    if (e < E) {
        int sZ = atomicAdd(&cntZ[dstZ[e]], 1);
        int sA = atomicAdd(&cntA[dstA[e]], 1);
        slotP[e] = (sZ << 16) | sA;
    }
}

__global__ __launch_bounds__(SCB) void block_sum_kernel(
    const int* __restrict__ cntZ, const int* __restrict__ cntA,
    int* __restrict__ partZ, int* __restrict__ partA, int n, int nblk)
{
    int b = blockIdx.x;
    const int* cnt = (b < nblk) ? cntZ : cntA;
    int*       prt = (b < nblk) ? partZ : partA;
    int bb = (b < nblk) ? b : b - nblk;
    int i = bb * SCB + threadIdx.x;
    int v = (i < n) ? cnt[i] : 0;
    #pragma unroll
    for (int d = 16; d; d >>= 1) v += __shfl_xor_sync(0xffffffffu, v, d);
    __shared__ int ws[SCB / 32];
    int lane = threadIdx.x & 31, w = threadIdx.x >> 5;
    if (lane == 0) ws[w] = v;
    __syncthreads();
    if (threadIdx.x < SCB / 32) {
        int s = ws[threadIdx.x];
        #pragma unroll
        for (int d = (SCB / 64); d; d >>= 1) s += __shfl_xor_sync((1u << (SCB / 32)) - 1u, s, d);
        if (threadIdx.x == 0) prt[bb] = s;
    }
}

__global__ __launch_bounds__(512) void scan_partials_kernel(
    int* __restrict__ partZ, int* __restrict__ partA, int nblk)
{
    int* part = blockIdx.x ? partA : partZ;
    int t = threadIdx.x;
    __shared__ int sm[512];
    int v = (t < nblk) ? part[t] : 0;
    sm[t] = v;
    __syncthreads();
    #pragma unroll
    for (int d = 1; d < 512; d <<= 1) {
        int u = (t >= d) ? sm[t - d] : 0;
        __syncthreads();
        sm[t] += u;
        __syncthreads();
    }
    if (t < nblk) part[t] = sm[t] - v;   // exclusive
}

__global__ __launch_bounds__(SCB) void scan_write_kernel(
    const int* __restrict__ cntZ, const int* __restrict__ partZ, int* __restrict__ rpZ,
    const int* __restrict__ cntA, const int* __restrict__ partA, int* __restrict__ rpA,
    int n, int nblk)
{
    int b = blockIdx.x;
    const int* cnt  = (b < nblk) ? cntZ : cntA;
    const int* prt  = (b < nblk) ? partZ : partA;
    int*       rp   = (b < nblk) ? rpZ : rpA;
    int bb = (b < nblk) ? b : b - nblk;
    int t = threadIdx.x;
    int i = bb * SCB + t;
    int v = (i < n) ? cnt[i] : 0;
    int lane = t & 31, w = t >> 5;
    int inc = v;
    #pragma unroll
    for (int d = 1; d < 32; d <<= 1) {
        int u = __shfl_up_sync(0xffffffffu, inc, d);
        if (lane >= d) inc += u;
    }
    __shared__ int wsum[SCB / 32];
    if (lane == 31) wsum[w] = inc;
    __syncthreads();
    if (t < SCB / 32) {
        int s = wsum[t];
        int sc = s;
        #pragma unroll
        for (int d = 1; d < SCB / 32; d <<= 1) {
            int u = __shfl_up_sync((1u << (SCB / 32)) - 1u, sc, d);
            if (t >= d) sc += u;
        }
        wsum[t] = sc - s;   // exclusive warp offset
    }
    __syncthreads();
    int excl = inc - v + wsum[w] + prt[bb];
    if (i < n) rp[i] = excl;
    if (i == n - 1) rp[n] = excl + v;
}

// atomic-free fill: pos = rp[dst] + slot
__global__ void fill_both_kernel(
    const int* __restrict__ srcZ, const int* __restrict__ dstZ, const float* __restrict__ valsZ,
    const int* __restrict__ srcA, const int* __restrict__ dstA, const float* __restrict__ valsA,
    const int* __restrict__ rpZ, const int* __restrict__ rpA,
    const int* __restrict__ slotP,
    int2* __restrict__ edgeZ, int2* __restrict__ edgeA, int E)
{
    int e = blockIdx.x * blockDim.x + threadIdx.x;
    if (e >= E) return;
    int sp = slotP[e];
    {
        int pos = __ldg(&rpZ[dstZ[e]]) + (sp >> 16);
        edgeZ[pos] = make_int2(srcZ[e], __float_as_int(valsZ[e]));
    }
    {
        int pos = __ldg(&rpA[dstA[e]]) + (sp & 0xffff);
        edgeA[pos] = make_int2(srcA[e], __float_as_int(valsA[e]));
    }
}

// ---------------------------------------------------------------------------
// Gather SpMM (128-wide, fp16 in/out): warp per node, lane owns 4 features.
// [R13-proven: sequential broadcast edge loads are L1-resident]
// ---------------------------------------------------------------------------
__global__ __launch_bounds__(256) void spmm_gather128h(
    const __half* __restrict__ X, const int2* __restrict__ edges,
    const int* __restrict__ rp, __half* __restrict__ Y, int n)
{
    int w = (blockIdx.x * 256 + (int)threadIdx.x) >> 5;
    if (w >= n) return;
    int lane = threadIdx.x & 31;
    int beg = rp[w], end = rp[w + 1];
    float4 acc = make_float4(0.f, 0.f, 0.f, 0.f);
    #pragma unroll 4
    for (int j = beg; j < end; j++) {
        int2 e = edges[j];
        float v = __int_as_float(e.y);
        uint2 u = *(const uint2*)(X + (size_t)e.x * NF + lane * 4);
        float2 f0 = __half22float2(*(__half2*)&u.x);
        float2 f1 = __half22float2(*(__half2*)&u.y);
        acc.x += v * f0.x; acc.y += v * f0.y;
        acc.z += v * f1.x; acc.w += v * f1.y;
    }
    uint2 o;
    *(__half2*)&o.x = __floats2half2_rn(acc.x, acc.y);
    *(__half2*)&o.y = __floats2half2_rn(acc.z, acc.w);
    *(uint2*)(Y + (size_t)w * NF + lane * 4) = o;
}

// ---------------------------------------------------------------------------
// Fused gather SpMM (40-wide, fp16) + bias + log_softmax.
// TWO nodes per warp: 16-lane groups, lanes 0..9 of each group own 4 classes.
// ---------------------------------------------------------------------------
__global__ __launch_bounds__(256) void spmm40_lsm_kernel(
    const __half* __restrict__ T, const int2* __restrict__ edges,
    const int* __restrict__ rp, const float* __restrict__ b2,
    float* __restrict__ out, int n)
{
    int w    = (blockIdx.x * 256 + (int)threadIdx.x) >> 5;
    int lane = threadIdx.x & 31;
    int grp  = lane >> 4;      // 0 or 1
    int l    = lane & 15;      // 0..15
    int node = w * 2 + grp;
    bool act = (l < 10) && (node < n);

    float4 acc = make_float4(0.f, 0.f, 0.f, 0.f);
    if (act) {
        int beg = rp[node], end = rp[node + 1];
        #pragma unroll 4
        for (int j = beg; j < end; j++) {
            int2 e = edges[j];
            float v = __int_as_float(e.y);
            uint2 u = *(const uint2*)(T + (size_t)e.x * NCLS + l * 4);
            float2 f0 = __half22float2(*(__half2*)&u.x);
            float2 f1 = __half22float2(*(__half2*)&u.y);
            acc.x += v * f0.x; acc.y += v * f0.y;
            acc.z += v * f1.x; acc.w += v * f1.y;
        }
        float4 bv = *(const float4*)(b2 + l * 4);
        acc.x += bv.x; acc.y += bv.y; acc.z += bv.z; acc.w += bv.w;
    }
    float m = act ? fmaxf(fmaxf(acc.x, acc.y), fmaxf(acc.z, acc.w)) : -INFINITY;
    #pragma unroll
    for (int d = 8; d; d >>= 1) m = fmaxf(m, __shfl_xor_sync(0xffffffffu, m, d, 16));
    float e = act ? (__expf(acc.x - m) + __expf(acc.y - m) +
                     __expf(acc.z - m) + __expf(acc.w - m)) : 0.f;
    #pragma unroll
    for (int d = 8; d; d >>= 1) e += __shfl_xor_sync(0xffffffffu, e, d, 16);
    float lse = logf(e) + m;
    if (act) {
        float4 o = make_float4(acc.x - lse, acc.y - lse, acc.z - lse, acc.w - lse);
        *(float4*)(out + (size_t)node * NCLS + l * 4) = o;
    }
}

// ---------------------------------------------------------------------------
// FP16 HMMA (m16n8k16) GEMM + bias + BN + ReLU -> fp16.
// BM=64, BN=128, BK=32 (same tiling as proven tf32 version).
// Pitch-40-half smem: fragment half2 bank = (20g%32)+t+c covers all 32 banks.
// Coalesced global loads: idx = q*256+tid -> 64B-contiguous per 8 lanes.
// No converts in the load phase (X and W both already fp16).
// ---------------------------------------------------------------------------
#define PH 40

__device__ __forceinline__ void mma_f16(float* c, const unsigned* a, unsigned b0, unsigned b1) {
    asm volatile(
        "mma.sync.aligned.m16n8k16.row.col.f32.f16.f16.f32 "
        "{%0,%1,%2,%3}, {%4,%5,%6,%7}, {%8,%9}, {%0,%1,%2,%3};"
        : "+f"(c[0]), "+f"(c[1]), "+f"(c[2]), "+f"(c[3])
        : "r"(a[0]), "r"(a[1]), "r"(a[2]), "r"(a[3]), "r"(b0), "r"(b1));
}

__device__ __forceinline__ unsigned ldh2(const __half* p) {
    return *(const unsigned*)p;
}

__global__ __launch_bounds__(256) void gemm_bn_relu_hmma(
    const __half* __restrict__ Xh, const __half* __restrict__ Wh,
    const float* __restrict__ bias, const float* __restrict__ gamma,
    const float* __restrict__ beta, const float* __restrict__ rmean,
    const float* __restrict__ rvar, const float* __restrict__ am,
    __half* __restrict__ Y, int n)
{
    __shared__ __half Xs[64][PH];    // 5.1 KB
    __shared__ __half Ws[128][PH];   // 10.2 KB
    __shared__ float s_sc[128], s_sh[128], s_bs[128];

    int tid  = threadIdx.x;
    int lane = tid & 31;
    int wid  = tid >> 5;
    int warp_m = wid & 1;
    int warp_n = wid >> 1;
    int m0 = blockIdx.x * 64;

    if (tid < 128) {
        float s = gamma[tid] * rsqrtf(rvar[tid] + 1e-5f);
        s_sc[tid] = s;
        s_sh[tid] = beta[tid] - rmean[tid] * s;
        s_bs[tid] = bias[tid];
    }

    float acc[2][4][4];
    #pragma unroll
    for (int i = 0; i < 2; i++)
        #pragma unroll
        for (int j = 0; j < 4; j++)
            #pragma unroll
            for (int q = 0; q < 4; q++) acc[i][j][q] = 0.f;

    int g = lane >> 2, t = lane & 3;

    for (int k0 = 0; k0 < NF; k0 += 32) {
        // X tile: 64 rows x 32 halves = 512 uint2, coalesced
        #pragma unroll
        for (int q = 0; q < 2; q++) {
            int idx = q * 256 + tid;
            int r   = idx >> 3;
            int kc  = (idx & 7) * 4;
            uint2 u = make_uint2(0u, 0u);
            int gr = m0 + r;
            if (gr < n) u = *(const uint2*)(Xh + (size_t)gr * NF + k0 + kc);
            *(uint2*)&Xs[r][kc] = u;
        }
        // W tile: 128 rows x 32 halves = 1024 uint2, coalesced
        #pragma unroll
        for (int q = 0; q < 4; q++) {
            int idx = q * 256 + tid;
            int o   = idx >> 3;
            int kc  = (idx & 7) * 4;
            *(uint2*)&Ws[o][kc] = *(const uint2*)(Wh + o * NF + k0 + kc);
        }
        __syncthreads();

        #pragma unroll
        for (int kk = 0; kk < 32; kk += 16) {
            unsigned a[2][4];
            #pragma unroll
            for (int ma = 0; ma < 2; ma++) {
                int rb = warp_m * 32 + ma * 16;
                a[ma][0] = ldh2(&Xs[rb + g    ][kk + 2 * t    ]);
                a[ma][1] = ldh2(&Xs[rb + g + 8][kk + 2 * t    ]);
                a[ma][2] = ldh2(&Xs[rb + g    ][kk + 2 * t + 8]);
                a[ma][3] = ldh2(&Xs[rb + g + 8][kk + 2 * t + 8]);
            }
            #pragma unroll
            for (int na = 0; na < 4; na++) {
                int nb = warp_n * 32 + na * 8;
                unsigned b0 = ldh2(&Ws[nb + g][kk + 2 * t    ]);
                unsigned b1 = ldh2(&Ws[nb + g][kk + 2 * t + 8]);
                mma_f16(acc[0][na], a[0], b0, b1);
                mma_f16(acc[1][na], a[1], b0, b1);
            }
        }
        __syncthreads();
    }

    #pragma unroll
    for (int ma = 0; ma < 2; ma++) {
        int r0 = m0 + warp_m * 32 + ma * 16 + g;
        int r1 = r0 + 8;
        float a0 = 1.f, a1 = 1.f;
        if (am != nullptr) {
            if (r0 < n) a0 = am[r0];
            if (r1 < n) a1 = am[r1];
        }
        #pragma unroll
        for (int na = 0; na < 4; na++) {
            int c = warp_n * 32 + na * 8 + 2 * t;
            float sc0 = s_sc[c], sc1 = s_sc[c + 1];
            float sh0 = s_sh[c], sh1 = s_sh[c + 1];
            float bs0 = s_bs[c], bs1 = s_bs[c + 1];
            if (r0 < n) {
                float ox = fmaxf((acc[ma][na][0] * a0 + bs0) * sc0 + sh0, 0.f);
                float oy = fmaxf((acc[ma][na][1] * a0 + bs1) * sc1 + sh1, 0.f);
                *(__half2*)(Y + (size_t)r0 * NF + c) = __floats2half2_rn(ox, oy);
            }
            if (r1 < n) {
                float ox = fmaxf((acc[ma][na][2] * a1 + bs0) * sc0 + sh0, 0.f);
                float oy = fmaxf((acc[ma][na][3] * a1 + bs1) * sc1 + sh1, 0.f);
                *(__half2*)(Y + (size_t)r1 * NF + c) = __floats2half2_rn(ox, oy);
            }
        }
    }
}

// ---------------------------------------------------------------------------
// FP16 HMMA: t = h1 @ W2^T (N x 40), fp16 in/out. 128 rows/block, 8 warps.
// ---------------------------------------------------------------------------
__global__ __launch_bounds__(256) void tgemm_hmma(
    const __half* __restrict__ Xh, const __half* __restrict__ W2h,
    __half* __restrict__ T, int n)
{
    __shared__ __half Xs[128][PH];   // 10.2 KB
    __shared__ __half Ws[NCLS][PH];  // 3.2 KB

    int tid  = threadIdx.x;
    int lane = tid & 31;
    int wid  = tid >> 5;
    int m0 = blockIdx.x * 128;
    int g = lane >> 2, t = lane & 3;

    float acc[5][4];
    #pragma unroll
    for (int i = 0; i < 5; i++)
        #pragma unroll
        for (int q = 0; q < 4; q++) acc[i][q] = 0.f;

    for (int k0 = 0; k0 < NF; k0 += 32) {
        // X tile: 128 rows x 32 halves = 1024 uint2, coalesced
        #pragma unroll
        for (int q = 0; q < 4; q++) {
            int idx = q * 256 + tid;
            int r   = idx >> 3;
            int kc  = (idx & 7) * 4;
            uint2 u = make_uint2(0u, 0u);
            int gr = m0 + r;
            if (gr < n) u = *(const uint2*)(Xh + (size_t)gr * NF + k0 + kc);
            *(uint2*)&Xs[r][kc] = u;
        }
        // W2 tile: 40 rows x 32 halves = 320 uint2
        for (int idx = tid; idx < NCLS * 8; idx += 256) {
            int o  = idx >> 3;
            int kc = (idx & 7) * 4;
            *(uint2*)&Ws[o][kc] = *(const uint2*)(W2h + o * NF + k0 + kc);
        }
        __syncthreads();

        #pragma unroll
        for (int kk = 0; kk < 32; kk += 16) {
            int rb = wid * 16;
            unsigned a[4];
            a[0] = ldh2(&Xs[rb + g    ][kk + 2 * t    ]);
            a[1] = ldh2(&Xs[rb + g + 8][kk + 2 * t    ]);
            a[2] = ldh2(&Xs[rb + g    ][kk + 2 * t + 8]);
            a[3] = ldh2(&Xs[rb + g + 8][kk + 2 * t + 8]);
            #pragma unroll
            for (int na = 0; na < 5; na++) {
                unsigned b0 = ldh2(&Ws[na * 8 + g][kk + 2 * t    ]);
                unsigned b1 = ldh2(&Ws[na * 8 + g][kk + 2 * t + 8]);
                mma_f16(acc[na], a, b0, b1);
            }
        }
        __syncthreads();
    }

    int r0 = m0 + wid * 16 + g;
    int r1 = r0 + 8;
    #pragma unroll
    for (int na = 0; na < 5; na++) {
        int c = na * 8 + 2 * t;
        if (r0 < n) *(__half2*)(T + (size_t)r0 * NCLS + c) = __floats2half2_rn(acc[na][0], acc[na][1]);
        if (r1 < n) *(__half2*)(T + (size_t)r1 * NCLS + c) = __floats2half2_rn(acc[na][2], acc[na][3]);
    }
}

// ---------------------------------------------------------------------------
// launch
// ---------------------------------------------------------------------------
extern "C" void kernel_launch(void* const* d_in, const int* in_sizes, int n_in,
                              void* d_out, int out_size)
{
    const float* x     = (const float*)d_in[0];
    const float* M     = (const float*)d_in[1];
    const float* AM    = (const float*)d_in[2];
    const int*   srcZ  = (const int*)  d_in[3];
    const int*   dstZ  = (const int*)  d_in[4];
    const float* valsZ = (const float*)d_in[5];
    const int*   src   = (const int*)  d_in[6];
    const int*   dst   = (const int*)  d_in[7];
    const float* vals  = (const float*)d_in[8];
    const float* W0  = (const float*)d_in[9];
    const float* b0  = (const float*)d_in[10];
    const float* g0  = (const float*)d_in[11];
    const float* be0 = (const float*)d_in[12];
    const float* rm0 = (const float*)d_in[13];
    const float* rv0 = (const float*)d_in[14];
    const float* W1  = (const float*)d_in[15];
    const float* b1  = (const float*)d_in[16];
    const float* g1  = (const float*)d_in[17];
    const float* be1 = (const float*)d_in[18];
    const float* rm1 = (const float*)d_in[19];
    const float* rv1 = (const float*)d_in[20];
    const float* W2  = (const float*)d_in[21];
    const float* b2  = (const float*)d_in[22];
    float* out = (float*)d_out;

    int n = in_sizes[1];
    int E = in_sizes[3];

    __half *hA, *hB, *t40h, *W0h, *W1h, *W2h;
    int *rpZ, *rpA, *cntZ, *cntA, *partZ, *partA, *slotP;
    int2 *edgeZ, *edgeA;
    cudaGetSymbolAddress((void**)&hA, g_hA);
    cudaGetSymbolAddress((void**)&hB, g_hB);
    cudaGetSymbolAddress((void**)&t40h, g_t40h);
    cudaGetSymbolAddress((void**)&W0h, g_W0h);
    cudaGetSymbolAddress((void**)&W1h, g_W1h);
    cudaGetSymbolAddress((void**)&W2h, g_W2h);
    cudaGetSymbolAddress((void**)&rpZ, g_rpZ);
    cudaGetSymbolAddress((void**)&rpA, g_rpA);
    cudaGetSymbolAddress((void**)&cntZ, g_cntZ);
    cudaGetSymbolAddress((void**)&cntA, g_cntA);
    cudaGetSymbolAddress((void**)&partZ, g_partZ);
    cudaGetSymbolAddress((void**)&partA, g_partA);
    cudaGetSymbolAddress((void**)&slotP, g_slotP);
    cudaGetSymbolAddress((void**)&edgeZ, g_edgeZ);
    cudaGetSymbolAddress((void**)&edgeA, g_edgeA);

    int egrid   = (E + 255) / 256;
    int ngrid   = (n + 255) / 256;
    int nblk    = (n + SCB - 1) / SCB;
    int wgrid   = (n * 32 + 255) / 256;               // warp per node
    int w2grid  = (((n + 1) / 2) * 32 + 255) / 256;   // 2 nodes per warp
    int ggrid   = (n + 63) / 64;
    int tggrid  = (n + 127) / 128;
    int pgrid   = (n * 32 + 255) / 256;
    int wq      = W0Q + W1Q + W2Q;

    // --- CSR build + fp16 pre-passes ---
    zero2_kernel<<<ngrid, 256>>>(cntZ, cntA, n);
    mxhalf_kernel<<<pgrid, 256>>>(x, M, hA, n);
    w2h_all_kernel<<<(wq + 255) / 256, 256>>>(W0, W0h, W1, W1h, W2, W2h);
    count_slot_kernel<<<egrid, 256>>>(dstZ, dst, cntZ, cntA, slotP, E);
    block_sum_kernel<<<2 * nblk, SCB>>>(cntZ, cntA, partZ, partA, n, nblk);
    scan_partials_kernel<<<2, 512>>>(partZ, partA, nblk);
    scan_write_kernel<<<2 * nblk, SCB>>>(cntZ, partZ, rpZ, cntA, partA, rpA, n, nblk);
    fill_both_kernel<<<egrid, 256>>>(srcZ, dstZ, valsZ, src, dst, vals,
                                     rpZ, rpA, slotP, edgeZ, edgeA, E);

    // --- layer 0 ---
    spmm_gather128h<<<wgrid, 256>>>(hA, edgeZ, rpZ, hB, n);
    gemm_bn_relu_hmma<<<ggrid, 256>>>(hB, W0h, b0, g0, be0, rm0, rv0, AM, hA, n);

    // --- layer 1 ---
    spmm_gather128h<<<wgrid, 256>>>(hA, edgeA, rpA, hB, n);
    gemm_bn_relu_hmma<<<ggrid, 256>>>(hB, W1h, b1, g1, be1, rm1, rv1, nullptr, hA, n);

    // --- layer 2 (commuted) ---
    tgemm_hmma<<<tggrid, 256>>>(hA, W2h, t40h, n);
    spmm40_lsm_kernel<<<w2grid, 256>>>(t40h, edgeA, rpA, b2, out, n);
}